// round 9
// baseline (speedup 1.0000x reference)
#include <cuda_runtime.h>
#include <cuda_fp16.h>
#include <math.h>

// Problem constants
#define CTRLN 256
#define WORDN 128
#define MEMN  128
#define DINN  64
#define BN    512
#define TN    512
#define GINN  192            // D_IN + WORD
#define EPSF  1e-6f

// ---------------- device scratch (static, no allocs) ----------------
__device__ __half g_WIH[24 * 768 * 8];    // [k8][o(768)][p(8)] halves, k = 8*k8+p
__device__ __half g_WHH[32 * 768 * 8];
__device__ __half g_WHD[32 * 512 * 8];    // head: key|erase|add|beta|pad

// ---------------- helpers ----------------
__device__ __forceinline__ void ffma2(float2 &d, float2 a, float2 b) {
    unsigned long long &du = reinterpret_cast<unsigned long long &>(d);
    unsigned long long au = reinterpret_cast<unsigned long long &>(a);
    unsigned long long bu = reinterpret_cast<unsigned long long &>(b);
    asm("fma.rn.f32x2 %0, %1, %2, %0;" : "+l"(du) : "l"(au), "l"(bu));
}
__device__ __forceinline__ float2 dup2(float a) { return make_float2(a, a); }
__device__ __forceinline__ float sigf(float x) {
    return __fdividef(1.0f, 1.0f + __expf(-x));
}
__device__ __forceinline__ float tanhf_fast(float x) {
    float ax = fabsf(x);
    float t = __expf(-2.0f * ax);
    float r = (1.0f - t) * __fdividef(1.0f, 1.0f + t);
    return copysignf(r, x);
}
__device__ __forceinline__ float softplusf(float x) {
    return fmaxf(x, 0.0f) + log1pf(__expf(-fabsf(x)));
}
__device__ __forceinline__ float sqrt_fast(float x) {
    float xs = x + 1e-30f;
    return xs * rsqrtf(xs);
}
#define BARN(id, cnt) asm volatile("bar.sync %0, %1;" :: "r"(id), "r"(cnt) : "memory")

// ---------------- K0: weight repack to fp16 ----------------
__global__ void ntm_prep(const float* __restrict__ W_ih, const float* __restrict__ W_hh,
                         const float* __restrict__ W_key, const float* __restrict__ W_beta,
                         const float* __restrict__ W_erase, const float* __restrict__ W_add) {
    int stride = gridDim.x * blockDim.x;
    int idx0 = blockIdx.x * blockDim.x + threadIdx.x;
    for (int i = idx0; i < 768 * 192; i += stride) {
        int o = i / 192, k = i % 192;
        g_WIH[((k >> 3) * 768 + o) * 8 + (k & 7)] = __float2half(W_ih[i]);
    }
    for (int i = idx0; i < 768 * 256; i += stride) {
        int o = i / 256, k = i % 256;
        g_WHH[((k >> 3) * 768 + o) * 8 + (k & 7)] = __float2half(W_hh[i]);
    }
    for (int i = idx0; i < 32 * 512 * 8; i += stride) {
        int k8 = i / (512 * 8);
        int r = i % (512 * 8);
        int o = r >> 3, p = r & 7;
        int k = k8 * 8 + p;
        float v = 0.0f;
        if (o < 128)       v = W_key[o * 256 + k];
        else if (o < 256)  v = W_erase[(o - 128) * 256 + k];
        else if (o < 384)  v = W_add[(o - 256) * 256 + k];
        else if (o == 384) v = W_beta[k];
        g_WHD[i] = __float2half(v);
    }
}

// ---------------- GEMV_P: gh (K=256) + gi_x (K=64) for output j, 4 elems ----------------
__device__ __forceinline__ void gemv_P(int j, float bR, float bZ, float bNi, float bNh,
                                       const float (*s_in)[4], const float (*s_h)[4],
                                       float (*s_redB)[256]) {
    float2 ar0 = dup2(bR), ar1 = dup2(bR);
    float2 az0 = dup2(bZ), az1 = dup2(bZ);
    float2 ai0 = dup2(bNi), ai1 = dup2(bNi);
    float2 ah0 = dup2(bNh), ah1 = dup2(bNh);
    {   // gi_x: k8 0..7 over x rows of s_in
        const uint4* W = (const uint4*)g_WIH;
        #pragma unroll 8
        for (int k8 = 0; k8 < 8; ++k8) {
            uint4 uwr = __ldg(&W[k8 * 768 + j]);
            uint4 uwz = __ldg(&W[k8 * 768 + 256 + j]);
            uint4 uwn = __ldg(&W[k8 * 768 + 512 + j]);
            const __half2* hr = (const __half2*)&uwr;
            const __half2* hz = (const __half2*)&uwz;
            const __half2* hn = (const __half2*)&uwn;
            #pragma unroll
            for (int q = 0; q < 4; ++q) {
                float2 wr2 = __half22float2(hr[q]);
                float2 wz2 = __half22float2(hz[q]);
                float2 wn2 = __half22float2(hn[q]);
                float4 ia = *(const float4*)&s_in[k8 * 8 + 2 * q][0];
                float4 ib = *(const float4*)&s_in[k8 * 8 + 2 * q + 1][0];
                float2 a01 = make_float2(ia.x, ia.y), a23 = make_float2(ia.z, ia.w);
                float2 b01 = make_float2(ib.x, ib.y), b23 = make_float2(ib.z, ib.w);
                ffma2(ar0, dup2(wr2.x), a01); ffma2(ar1, dup2(wr2.x), a23);
                ffma2(az0, dup2(wz2.x), a01); ffma2(az1, dup2(wz2.x), a23);
                ffma2(ai0, dup2(wn2.x), a01); ffma2(ai1, dup2(wn2.x), a23);
                ffma2(ar0, dup2(wr2.y), b01); ffma2(ar1, dup2(wr2.y), b23);
                ffma2(az0, dup2(wz2.y), b01); ffma2(az1, dup2(wz2.y), b23);
                ffma2(ai0, dup2(wn2.y), b01); ffma2(ai1, dup2(wn2.y), b23);
            }
        }
    }
    {   // gh: k8 0..31 over s_h
        const uint4* W = (const uint4*)g_WHH;
        #pragma unroll 8
        for (int k8 = 0; k8 < 32; ++k8) {
            uint4 uwr = __ldg(&W[k8 * 768 + j]);
            uint4 uwz = __ldg(&W[k8 * 768 + 256 + j]);
            uint4 uwn = __ldg(&W[k8 * 768 + 512 + j]);
            const __half2* hr = (const __half2*)&uwr;
            const __half2* hz = (const __half2*)&uwz;
            const __half2* hn = (const __half2*)&uwn;
            #pragma unroll
            for (int q = 0; q < 4; ++q) {
                float2 wr2 = __half22float2(hr[q]);
                float2 wz2 = __half22float2(hz[q]);
                float2 wn2 = __half22float2(hn[q]);
                float4 ia = *(const float4*)&s_h[k8 * 8 + 2 * q][0];
                float4 ib = *(const float4*)&s_h[k8 * 8 + 2 * q + 1][0];
                float2 a01 = make_float2(ia.x, ia.y), a23 = make_float2(ia.z, ia.w);
                float2 b01 = make_float2(ib.x, ib.y), b23 = make_float2(ib.z, ib.w);
                ffma2(ar0, dup2(wr2.x), a01); ffma2(ar1, dup2(wr2.x), a23);
                ffma2(az0, dup2(wz2.x), a01); ffma2(az1, dup2(wz2.x), a23);
                ffma2(ah0, dup2(wn2.x), a01); ffma2(ah1, dup2(wn2.x), a23);
                ffma2(ar0, dup2(wr2.y), b01); ffma2(ar1, dup2(wr2.y), b23);
                ffma2(az0, dup2(wz2.y), b01); ffma2(az1, dup2(wz2.y), b23);
                ffma2(ah0, dup2(wn2.y), b01); ffma2(ah1, dup2(wn2.y), b23);
            }
        }
    }
    s_redB[0][j] = ar0.x;  s_redB[1][j] = ar0.y;  s_redB[2][j] = ar1.x;  s_redB[3][j] = ar1.y;
    s_redB[4][j] = az0.x;  s_redB[5][j] = az0.y;  s_redB[6][j] = az1.x;  s_redB[7][j] = az1.y;
    s_redB[8][j] = ai0.x;  s_redB[9][j] = ai0.y;  s_redB[10][j] = ai1.x; s_redB[11][j] = ai1.y;
    s_redB[12][j] = ah0.x; s_redB[13][j] = ah0.y; s_redB[14][j] = ah1.x; s_redB[15][j] = ah1.y;
}

#define SMEM_TOTAL (52288 + 4 * MEMN * WORDN * 2)   // 183360 bytes

// ---------------- K1: persistent pipelined kernel, M in SMEM ----------------
__global__ __launch_bounds__(512, 1)
void ntm_main(const float* __restrict__ data, const int* __restrict__ batch_sizes,
              const int* __restrict__ unsort_idxs,
              const float* __restrict__ b_ih, const float* __restrict__ b_hh,
              const float* __restrict__ b_key, const float* __restrict__ b_beta,
              const float* __restrict__ b_erase, const float* __restrict__ b_add,
              const float* __restrict__ M0, float* __restrict__ out) {
    extern __shared__ __align__(16) unsigned char dsm[];
    float (*s_in)[4]        = (float(*)[4])(dsm);              // [192][4]
    float (*s_h)[4]         = (float(*)[4])(dsm + 3072);       // [256][4]
    float (*s_redA)[256]    = (float(*)[256])(dsm + 7168);     // [12][256]
    float (*s_redB)[256]    = (float(*)[256])(dsm + 19456);    // [16][256]
    float (*s_key)[128]     = (float(*)[128])(dsm + 35840);    // [4][128]
    float (*s_e)[128]       = (float(*)[128])(dsm + 37888);
    float (*s_a)[128]       = (float(*)[128])(dsm + 39936);
    float (*s_w)[128]       = (float(*)[128])(dsm + 41984);
    float (*s_racc)[2][128] = (float(*)[2][128])(dsm + 44032); // [4][2][128]
    float* s_beta           = (float*)(dsm + 52224);
    int*   s_len            = (int*)(dsm + 52240);
    int*   s_dst            = (int*)(dsm + 52256);
    __half* s_M             = (__half*)(dsm + 52288);          // [4][128][128] fp16

    const int tid = threadIdx.x;
    const int lane = tid & 31;
    const int warp = tid >> 5;
    const int b0 = blockIdx.x * 4;
    const int j = tid & 255;
    const int sk = tid >> 8;     // 0 = MEM warps (0-7), 1 = GEMV warps (8-15)

    // ---- active lengths ----
    if (warp < 4) {
        int e = warp, cnt = 0;
        for (int t = lane; t < TN; t += 32) cnt += (batch_sizes[t] > (b0 + e)) ? 1 : 0;
        #pragma unroll
        for (int s = 16; s; s >>= 1) cnt += __shfl_xor_sync(0xffffffffu, cnt, s);
        if (lane == 0) s_len[e] = cnt;
    }
    // ---- init M in SMEM from M0 (fp32 -> fp16), 4 copies ----
    for (int i = tid; i < (MEMN * WORDN) / 2; i += 512) {
        float2 f = ((const float2*)M0)[i];
        __half2 h = __floats2half2_rn(f.x, f.y);
        #pragma unroll
        for (int e = 0; e < 4; e++)
            ((__half2*)s_M)[e * ((MEMN * WORDN) / 2) + i] = h;
    }
    for (int i = tid; i < GINN * 4; i += 512) (&s_in[0][0])[i] = 0.0f;
    for (int i = tid; i < CTRLN * 4; i += 512) (&s_h[0][0])[i] = 0.0f;
    for (int i = tid; i < 16 * 256; i += 512) (&s_redB[0][0])[i] = 0.0f;

    // ---- biases ----
    float bR = 0.f, bZ = 0.f, bNi = 0.f, bNh = 0.f;   // GEMV warps
    if (sk == 1) {
        bR = b_ih[j] + b_hh[j];
        bZ = b_ih[256 + j] + b_hh[256 + j];
        bNi = b_ih[512 + j];
        bNh = b_hh[512 + j];
    }
    float bH1 = 0.f, bH2 = 0.f;                       // MEM warps (head outputs tid, 256+tid)
    if (sk == 0) {
        bH1 = (tid < 128) ? b_key[tid] : b_erase[tid - 128];
        bH2 = (tid < 128) ? b_add[tid] : ((tid == 128) ? b_beta[0] : 0.0f);
    }

    // ---- module roles (MEM warps): 2 warps per elem ----
    const int me = warp >> 1;       // elem (valid for warps 0-7)
    const int half = warp & 1;

    // ---- x prefetch prologue ----
    const int xe = tid >> 6, xd = tid & 63;           // valid for tid<256
    float xreg = 0.f;
    if (tid < 256) xreg = data[((size_t)0 * BN + (b0 + xe)) * DINN + xd];   // x_0
    __syncthreads();

    const int L0 = s_len[0], L1 = s_len[1], L2 = s_len[2], L3 = s_len[3];
    const int Tmax = max(max(L0, L1), max(L2, L3));

    if (tid < 256) {
        s_in[xd][xe] = xreg;                                                // x_0 -> smem
        xreg = data[((size_t)1 * BN + (b0 + xe)) * DINN + xd];              // x_1 -> reg
    }
    __syncthreads();
    // prologue pipelined GEMV: P_0 = gh(h=0) + gi_x(x_0) + biases
    if (sk == 1) gemv_P(j, bR, bZ, bNi, bNh, s_in, s_h, s_redB);
    __syncthreads();

    for (int t = 0; t < Tmax; ++t) {
        // ============ SERIAL PHASE ============
        if (sk == 1) {
            // GEMV warps: gi_read full (K=128, rows 64-191), one output each
            float2 gr0 = make_float2(0.f, 0.f), gr1 = make_float2(0.f, 0.f);
            float2 gz0 = make_float2(0.f, 0.f), gz1 = make_float2(0.f, 0.f);
            float2 gi0 = make_float2(0.f, 0.f), gi1 = make_float2(0.f, 0.f);
            const uint4* W = (const uint4*)g_WIH;
            #pragma unroll 8
            for (int k8 = 8; k8 < 24; ++k8) {
                uint4 uwr = __ldg(&W[k8 * 768 + j]);
                uint4 uwz = __ldg(&W[k8 * 768 + 256 + j]);
                uint4 uwn = __ldg(&W[k8 * 768 + 512 + j]);
                const __half2* hr = (const __half2*)&uwr;
                const __half2* hz = (const __half2*)&uwz;
                const __half2* hn = (const __half2*)&uwn;
                #pragma unroll
                for (int q = 0; q < 4; ++q) {
                    float2 wr2 = __half22float2(hr[q]);
                    float2 wz2 = __half22float2(hz[q]);
                    float2 wn2 = __half22float2(hn[q]);
                    float4 ia = *(const float4*)&s_in[k8 * 8 + 2 * q][0];
                    float4 ib = *(const float4*)&s_in[k8 * 8 + 2 * q + 1][0];
                    float2 a01 = make_float2(ia.x, ia.y), a23 = make_float2(ia.z, ia.w);
                    float2 b01 = make_float2(ib.x, ib.y), b23 = make_float2(ib.z, ib.w);
                    ffma2(gr0, dup2(wr2.x), a01); ffma2(gr1, dup2(wr2.x), a23);
                    ffma2(gz0, dup2(wz2.x), a01); ffma2(gz1, dup2(wz2.x), a23);
                    ffma2(gi0, dup2(wn2.x), a01); ffma2(gi1, dup2(wn2.x), a23);
                    ffma2(gr0, dup2(wr2.y), b01); ffma2(gr1, dup2(wr2.y), b23);
                    ffma2(gz0, dup2(wz2.y), b01); ffma2(gz1, dup2(wz2.y), b23);
                    ffma2(gi0, dup2(wn2.y), b01); ffma2(gi1, dup2(wn2.y), b23);
                }
            }
            s_redA[0][j] = gr0.x;  s_redA[1][j] = gr0.y;  s_redA[2][j] = gr1.x;  s_redA[3][j] = gr1.y;
            s_redA[4][j] = gz0.x;  s_redA[5][j] = gz0.y;  s_redA[6][j] = gz1.x;  s_redA[7][j] = gz1.y;
            s_redA[8][j] = gi0.x;  s_redA[9][j] = gi0.y;  s_redA[10][j] = gi1.x; s_redA[11][j] = gi1.y;
        } else {
            // MEM warps: deferred M-update for step t-1 (e = me, rows half*64..)
            if (t > 0 && (t - 1) < s_len[me]) {
                const int e = me;
                __half* Mw = s_M + e * (MEMN * WORDN) + lane * 4;
                float4 e4 = *(const float4*)&s_e[e][lane * 4];
                float4 a4 = *(const float4*)&s_a[e][lane * 4];
                float2 e01 = make_float2(-e4.x, -e4.y), e23 = make_float2(-e4.z, -e4.w);
                float2 a01 = make_float2(a4.x, a4.y),   a23 = make_float2(a4.z, a4.w);
                #pragma unroll 8
                for (int m = half * 64; m < half * 64 + 64; ++m) {
                    float wm = s_w[e][m];
                    float2 wm2 = dup2(wm);
                    uint2 u = *(uint2*)(Mw + m * WORDN);
                    __half2* hp = (__half2*)&u;
                    float2 m01 = __half22float2(hp[0]);
                    float2 m23 = __half22float2(hp[1]);
                    float2 f01 = make_float2(1.f, 1.f), f23 = make_float2(1.f, 1.f);
                    ffma2(f01, wm2, e01);            // 1 - wm*e
                    ffma2(f23, wm2, e23);
                    float2 w01 = make_float2(0.f, 0.f), w23 = make_float2(0.f, 0.f);
                    ffma2(w01, wm2, a01);            // wm*a
                    ffma2(w23, wm2, a23);
                    ffma2(w01, m01, f01);            // m*(1-wm*e) + wm*a
                    ffma2(w23, m23, f23);
                    hp[0] = __floats2half2_rn(w01.x, w01.y);
                    hp[1] = __floats2half2_rn(w23.x, w23.y);
                    *(uint2*)(Mw + m * WORDN) = u;
                }
            }
        }
        __syncthreads();   // B1: gi_read + M-update done

        // ---- gates + x-store (MEM warps) ----
        if (sk == 0) {
            float4 hold = *(const float4*)&s_h[j][0];
            float ho[4] = {hold.x, hold.y, hold.z, hold.w};
            float hn_[4];
            #pragma unroll
            for (int e = 0; e < 4; e++) {
                float ppr = s_redA[e][j] + s_redB[e][j];
                float ppz = s_redA[4 + e][j] + s_redB[4 + e][j];
                float ppi = s_redA[8 + e][j] + s_redB[8 + e][j];
                float pph = s_redB[12 + e][j];
                float r = sigf(ppr);
                float z = sigf(ppz);
                float n = tanhf_fast(ppi + r * pph);
                hn_[e] = (1.0f - z) * n + z * ho[e];
            }
            if (t < L0) s_h[j][0] = hn_[0];
            if (t < L1) s_h[j][1] = hn_[1];
            if (t < L2) s_h[j][2] = hn_[2];
            if (t < L3) s_h[j][3] = hn_[3];
            // x_{t+1} -> smem, prefetch x_{t+2}
            s_in[xd][xe] = xreg;
            int tn = min(t + 2, TN - 1);
            xreg = data[((size_t)tn * BN + (b0 + xe)) * DINN + xd];
        }
        __syncthreads();   // B2: h_t and x_{t+1} ready

        // ============ PARALLEL SEGMENT ============
        if (sk == 1) {
            // GEMV warps: P_{t+1} = gh(h_t) + gi_x(x_{t+1}) + biases
            gemv_P(j, bR, bZ, bNi, bNh, s_in, s_h, s_redB);
        } else {
            // ---- MEM warps: head GEMV (outputs tid, 256+tid; K=256) ----
            float2 h10 = dup2(bH1), h11 = dup2(bH1);
            float2 h20 = dup2(bH2), h21 = dup2(bH2);
            {
                const uint4* W = (const uint4*)g_WHD;
                #pragma unroll 8
                for (int k8 = 0; k8 < 32; ++k8) {
                    uint4 uw1 = __ldg(&W[k8 * 512 + tid]);
                    uint4 uw2 = __ldg(&W[k8 * 512 + 256 + tid]);
                    const __half2* h1p = (const __half2*)&uw1;
                    const __half2* h2p = (const __half2*)&uw2;
                    #pragma unroll
                    for (int q = 0; q < 4; ++q) {
                        float2 w12 = __half22float2(h1p[q]);
                        float2 w22 = __half22float2(h2p[q]);
                        float4 ia = *(const float4*)&s_h[k8 * 8 + 2 * q][0];
                        float4 ib = *(const float4*)&s_h[k8 * 8 + 2 * q + 1][0];
                        float2 a01 = make_float2(ia.x, ia.y), a23 = make_float2(ia.z, ia.w);
                        float2 b01 = make_float2(ib.x, ib.y), b23 = make_float2(ib.z, ib.w);
                        ffma2(h10, dup2(w12.x), a01); ffma2(h11, dup2(w12.x), a23);
                        ffma2(h20, dup2(w22.x), a01); ffma2(h21, dup2(w22.x), a23);
                        ffma2(h10, dup2(w12.y), b01); ffma2(h11, dup2(w12.y), b23);
                        ffma2(h20, dup2(w22.y), b01); ffma2(h21, dup2(w22.y), b23);
                    }
                }
            }
            {
                float v1[4] = {h10.x, h10.y, h11.x, h11.y};
                float v2[4] = {h20.x, h20.y, h21.x, h21.y};
                #pragma unroll
                for (int e = 0; e < 4; e++) {
                    if (tid < 128) {
                        s_key[e][tid] = tanhf_fast(v1[e]);   // raw key
                        s_a[e][tid] = v2[e];
                    } else {
                        s_e[e][tid - 128] = sigf(v1[e]);
                        if (tid == 128) s_beta[e] = softplusf(v2[e]);
                    }
                }
            }
            BARN(5, 256);   // all head outputs visible to all MEM warps

            const int e = me;
            if (t < s_len[e]) {
                // ---- pass 1: dot(M, k_raw)/(||M||+eps), M from SMEM, 64 rows/warp ----
                const __half* Me = s_M + e * (MEMN * WORDN);
                {
                    int rl = lane >> 3;
                    int cc = (lane & 7) * 16;
                    float2 kx[8];
                    #pragma unroll
                    for (int i = 0; i < 8; i++)
                        kx[i] = make_float2(s_key[e][cc + 2 * i], s_key[e][cc + 2 * i + 1]);
                    #pragma unroll 4
                    for (int mb = half * 64; mb < half * 64 + 64; mb += 4) {
                        int m = mb + rl;
                        const uint4* Mr = (const uint4*)(Me + m * WORDN + cc);
                        uint4 u0 = Mr[0];
                        uint4 u1 = Mr[1];
                        const __half2* p0 = (const __half2*)&u0;
                        const __half2* p1 = (const __half2*)&u1;
                        float2 d2 = make_float2(0.f, 0.f), n2 = make_float2(0.f, 0.f);
                        #pragma unroll
                        for (int q = 0; q < 4; q++) {
                            float2 f0 = __half22float2(p0[q]);
                            float2 f1 = __half22float2(p1[q]);
                            ffma2(d2, f0, kx[q]);
                            ffma2(n2, f0, f0);
                            ffma2(d2, f1, kx[4 + q]);
                            ffma2(n2, f1, f1);
                        }
                        float dot = d2.x + d2.y, nrm = n2.x + n2.y;
                        #pragma unroll
                        for (int s = 1; s < 8; s <<= 1) {
                            dot += __shfl_xor_sync(0xffffffffu, dot, s);
                            nrm += __shfl_xor_sync(0xffffffffu, nrm, s);
                        }
                        if ((lane & 7) == 0) s_w[e][m] = __fdividef(dot, sqrt_fast(nrm) + EPSF);
                    }
                }
                BARN(1 + e, 64);
                // ---- softmax (half==0 warp): scale = beta / (||k||+eps) ----
                if (half == 0) {
                    float q0 = s_key[e][lane];
                    float q1 = s_key[e][lane + 32];
                    float q2 = s_key[e][lane + 64];
                    float q3 = s_key[e][lane + 96];
                    float ss = q0 * q0 + q1 * q1 + q2 * q2 + q3 * q3;
                    #pragma unroll
                    for (int s = 16; s; s >>= 1) ss += __shfl_xor_sync(0xffffffffu, ss, s);
                    float scale = __fdividef(s_beta[e], sqrt_fast(ss) + EPSF);
                    float v0 = scale * s_w[e][lane];
                    float v1 = scale * s_w[e][lane + 32];
                    float v2 = scale * s_w[e][lane + 64];
                    float v3 = scale * s_w[e][lane + 96];
                    float mx = fmaxf(fmaxf(v0, v1), fmaxf(v2, v3));
                    #pragma unroll
                    for (int s = 16; s; s >>= 1) mx = fmaxf(mx, __shfl_xor_sync(0xffffffffu, mx, s));
                    v0 = __expf(v0 - mx); v1 = __expf(v1 - mx);
                    v2 = __expf(v2 - mx); v3 = __expf(v3 - mx);
                    float sum = v0 + v1 + v2 + v3;
                    #pragma unroll
                    for (int s = 16; s; s >>= 1) sum += __shfl_xor_sync(0xffffffffu, sum, s);
                    float inv = __fdividef(1.0f, sum);
                    s_w[e][lane] = v0 * inv;
                    s_w[e][lane + 32] = v1 * inv;
                    s_w[e][lane + 64] = v2 * inv;
                    s_w[e][lane + 96] = v3 * inv;
                }
                BARN(1 + e, 64);
                // ---- pass 2 (read only): read += w_m * M_m (M-update deferred) ----
                {
                    const __half* Mw = s_M + e * (MEMN * WORDN) + lane * 4;
                    float2 r01 = make_float2(0.f, 0.f), r23 = make_float2(0.f, 0.f);
                    #pragma unroll 8
                    for (int m = half * 64; m < half * 64 + 64; ++m) {
                        float wm = s_w[e][m];
                        float2 wm2 = dup2(wm);
                        uint2 u = *(const uint2*)(Mw + m * WORDN);
                        const __half2* hp = (const __half2*)&u;
                        float2 m01 = __half22float2(hp[0]);
                        float2 m23 = __half22float2(hp[1]);
                        ffma2(r01, wm2, m01);
                        ffma2(r23, wm2, m23);
                    }
                    *(float4*)&s_racc[e][half][lane * 4] =
                        make_float4(r01.x, r01.y, r23.x, r23.y);
                }
                BARN(1 + e, 64);
                // ---- combine read halves -> s_in rows 64.. ----
                {
                    int w = half * 32 + lane;
                    s_in[64 + w][e] = s_racc[e][0][w] + s_racc[e][1][w];
                    int w2 = w + 64;
                    s_in[64 + w2][e] = s_racc[e][0][w2] + s_racc[e][1][w2];
                }
            }
        }
        __syncthreads();   // B4: join
    }

    // ---- epilogue ----
    for (int q = tid; q < BN; q += 512) {
        int u = unsort_idxs[q];
        if (u >= b0 && u < b0 + 4) s_dst[u - b0] = q;
    }
    __syncthreads();
    if (tid < 256) {
        #pragma unroll
        for (int e = 0; e < 4; e++)
            out[(size_t)s_dst[e] * CTRLN + tid] = s_h[tid][e];
    }
    {
        int e = tid >> 7, w = tid & 127;
        if (tid < 512)
            out[(size_t)BN * CTRLN + (size_t)s_dst[e] * WORDN + w] = s_in[64 + w][e];
    }
}

// ---------------- launch ----------------
extern "C" void kernel_launch(void* const* d_in, const int* in_sizes, int n_in,
                              void* d_out, int out_size) {
    const float* data        = (const float*)d_in[0];
    const int*   batch_sizes = (const int*)d_in[1];
    const int*   unsort      = (const int*)d_in[2];
    const float* W_ih        = (const float*)d_in[3];
    const float* b_ih        = (const float*)d_in[4];
    const float* W_hh        = (const float*)d_in[5];
    const float* b_hh        = (const float*)d_in[6];
    const float* W_key       = (const float*)d_in[7];
    const float* b_key       = (const float*)d_in[8];
    const float* W_beta      = (const float*)d_in[9];
    const float* b_beta      = (const float*)d_in[10];
    const float* W_erase     = (const float*)d_in[11];
    const float* b_erase     = (const float*)d_in[12];
    const float* W_add       = (const float*)d_in[13];
    const float* b_add       = (const float*)d_in[14];
    const float* M0          = (const float*)d_in[15];

    cudaFuncSetAttribute(ntm_main, cudaFuncAttributeMaxDynamicSharedMemorySize, SMEM_TOTAL);
    ntm_prep<<<256, 256>>>(W_ih, W_hh, W_key, W_beta, W_erase, W_add);
    ntm_main<<<128, 512, SMEM_TOTAL>>>(data, batch_sizes, unsort,
                                       b_ih, b_hh, b_key, b_beta, b_erase, b_add,
                                       M0, (float*)d_out);
}

// round 11
// speedup vs baseline: 1.3311x; 1.3311x over previous
#include <cuda_runtime.h>
#include <cuda_fp16.h>
#include <stdint.h>
#include <math.h>

#define CTRLN 256
#define WORDN 128
#define MEMN  128
#define DINN  64
#define BN    512
#define TN    512
#define EPSF  1e-6f

#define STRX 200   // s_inh row stride (halves), bank-spread
#define STRH 264   // s_hHf row stride (halves)

// fragment-major fp16 weights
__device__ __half gA[16 * 3 * 28 * 256];   // GRU: [mpos][gate][ktile] x 256 halves/tile
__device__ __half gAH[32 * 16 * 256];      // head: [htile][ktile] x 256 halves/tile

// ---------------- helpers ----------------
__device__ __forceinline__ void ffma2(float2 &d, float2 a, float2 b) {
    unsigned long long &du = reinterpret_cast<unsigned long long &>(d);
    unsigned long long au = reinterpret_cast<unsigned long long &>(a);
    unsigned long long bu = reinterpret_cast<unsigned long long &>(b);
    asm("fma.rn.f32x2 %0, %1, %2, %0;" : "+l"(du) : "l"(au), "l"(bu));
}
__device__ __forceinline__ float2 dup2(float a) { return make_float2(a, a); }
__device__ __forceinline__ float sigf(float x) {
    return __fdividef(1.0f, 1.0f + __expf(-x));
}
__device__ __forceinline__ float tanhf_fast(float x) {
    float ax = fabsf(x);
    float t = __expf(-2.0f * ax);
    float r = (1.0f - t) * __fdividef(1.0f, 1.0f + t);
    return copysignf(r, x);
}
__device__ __forceinline__ float softplusf(float x) {
    return fmaxf(x, 0.0f) + log1pf(__expf(-fabsf(x)));
}
__device__ __forceinline__ float sqrt_fast(float x) {
    float xs = x + 1e-30f;
    return xs * rsqrtf(xs);
}
#define BARN(id, cnt) asm volatile("bar.sync %0, %1;" :: "r"(id), "r"(cnt) : "memory")

#define MMA(C, A, B0, B1) \
    asm volatile("mma.sync.aligned.m16n8k16.row.col.f32.f16.f16.f32 " \
        "{%0,%1,%2,%3},{%4,%5,%6,%7},{%8,%9},{%0,%1,%2,%3};" \
        : "+f"((C)[0]), "+f"((C)[1]), "+f"((C)[2]), "+f"((C)[3]) \
        : "r"((A).x), "r"((A).y), "r"((A).z), "r"((A).w), "r"(B0), "r"(B1))

// ---------------- K0: repack weights to fragment-major fp16 ----------------
__global__ void ntm_prep(const float* __restrict__ W_ih, const float* __restrict__ W_hh,
                         const float* __restrict__ W_key, const float* __restrict__ W_beta,
                         const float* __restrict__ W_erase, const float* __restrict__ W_add) {
    int stride = gridDim.x * blockDim.x;
    int idx0 = blockIdx.x * blockDim.x + threadIdx.x;
    // GRU tiles
    for (int i = idx0; i < 16 * 3 * 28 * 256; i += stride) {
        int tile = i >> 8, rem = i & 255;
        int lane = rem >> 3, p = rem & 7;
        int gid = lane >> 2, tig = lane & 3;
        int reg = p >> 1, w = p & 1;
        int r = gid + (reg & 1) * 8;
        int k = 2 * tig + (reg >> 1) * 8 + w;
        int mt = tile / 84, g = (tile / 28) % 3, kt = tile % 28;
        int o = g * 256 + mt * 16 + r;
        float v = (kt < 12) ? W_ih[o * 192 + kt * 16 + k]
                            : W_hh[o * 256 + (kt - 12) * 16 + k];
        gA[i] = __float2half(v);
    }
    // head tiles
    for (int i = idx0; i < 32 * 16 * 256; i += stride) {
        int tile = i >> 8, rem = i & 255;
        int lane = rem >> 3, p = rem & 7;
        int gid = lane >> 2, tig = lane & 3;
        int reg = p >> 1, w = p & 1;
        int r = gid + (reg & 1) * 8;
        int k = 2 * tig + (reg >> 1) * 8 + w;
        int ht = tile / 16, kt = tile % 16;
        int o = ht * 16 + r;
        int kk = kt * 16 + k;
        float v = 0.0f;
        if (o < 128)       v = W_key[o * 256 + kk];
        else if (o < 256)  v = W_erase[(o - 128) * 256 + kk];
        else if (o < 384)  v = W_add[(o - 256) * 256 + kk];
        else if (o == 384) v = W_beta[kk];
        gAH[i] = __float2half(v);
    }
}

// ---------------- pipelined mma: gh(h) + gi_x(x) for 2 m-positions ----------------
__device__ __forceinline__ void pipe_mma(int warp, int lane, int gid, int tig,
                                         const __half* __restrict__ s_inh,
                                         const __half* __restrict__ s_hHf,
                                         float* __restrict__ red) {
    const int mp0 = (warp - 8) * 2;
    float C[2][4][4];
    #pragma unroll
    for (int m = 0; m < 2; m++)
        #pragma unroll
        for (int a = 0; a < 4; a++)
            #pragma unroll
            for (int c = 0; c < 4; c++) C[m][a][c] = 0.0f;
    const uint4* A = (const uint4*)gA;
    // gi_x: k-tiles 0..3 (x rows of s_inh)
    #pragma unroll 2
    for (int kt = 0; kt < 4; ++kt) {
        uint32_t b0 = *(const uint32_t*)(s_inh + gid * STRX + kt * 16 + 2 * tig);
        uint32_t b1 = *(const uint32_t*)(s_inh + gid * STRX + kt * 16 + 2 * tig + 8);
        #pragma unroll
        for (int m = 0; m < 2; m++) {
            int mp = mp0 + m;
            uint4 ar = __ldg(&A[(size_t)((mp * 3 + 0) * 28 + kt) * 32 + lane]);
            uint4 az = __ldg(&A[(size_t)((mp * 3 + 1) * 28 + kt) * 32 + lane]);
            uint4 an = __ldg(&A[(size_t)((mp * 3 + 2) * 28 + kt) * 32 + lane]);
            MMA(C[m][0], ar, b0, b1);
            MMA(C[m][1], az, b0, b1);
            MMA(C[m][2], an, b0, b1);
        }
    }
    // gh: k-tiles 0..15 over s_hHf (n-gate -> nh accumulator)
    #pragma unroll 2
    for (int kt = 0; kt < 16; ++kt) {
        uint32_t b0 = *(const uint32_t*)(s_hHf + gid * STRH + kt * 16 + 2 * tig);
        uint32_t b1 = *(const uint32_t*)(s_hHf + gid * STRH + kt * 16 + 2 * tig + 8);
        #pragma unroll
        for (int m = 0; m < 2; m++) {
            int mp = mp0 + m;
            uint4 ar = __ldg(&A[(size_t)((mp * 3 + 0) * 28 + 12 + kt) * 32 + lane]);
            uint4 az = __ldg(&A[(size_t)((mp * 3 + 1) * 28 + 12 + kt) * 32 + lane]);
            uint4 an = __ldg(&A[(size_t)((mp * 3 + 2) * 28 + 12 + kt) * 32 + lane]);
            MMA(C[m][0], ar, b0, b1);
            MMA(C[m][1], az, b0, b1);
            MMA(C[m][3], an, b0, b1);
        }
    }
    if (tig < 2) {
        int e0 = 2 * tig;
        #pragma unroll
        for (int m = 0; m < 2; m++) {
            int j0 = (mp0 + m) * 16 + gid;
            #pragma unroll
            for (int a = 0; a < 4; a++) {
                *(float2*)&red[(a * 256 + j0) * 4 + e0] = make_float2(C[m][a][0], C[m][a][1]);
                *(float2*)&red[(a * 256 + j0 + 8) * 4 + e0] = make_float2(C[m][a][2], C[m][a][3]);
            }
        }
    }
}

#define SMEM_TOTAL (42304 + 4 * MEMN * WORDN * 2)   // 173376 bytes

// ---------------- K1: persistent tensor-core kernel ----------------
__global__ __launch_bounds__(512, 1)
void ntm_main(const float* __restrict__ data, const int* __restrict__ batch_sizes,
              const int* __restrict__ unsort_idxs,
              const float* __restrict__ b_ih, const float* __restrict__ b_hh,
              const float* __restrict__ b_key, const float* __restrict__ b_beta,
              const float* __restrict__ b_erase, const float* __restrict__ b_add,
              const float* __restrict__ M0, float* __restrict__ out) {
    extern __shared__ __align__(16) unsigned char dsm[];
    __half* s_inh           = (__half*)(dsm);                  // [8][STRX]: 0..63 x, 64..191 read
    __half* s_hHf           = (__half*)(dsm + 3200);           // [8][STRH] fp16 h
    float*  red             = (float*)(dsm + 7424);            // [4 acc][256 j][4 e]
    float (*s_key)[128]     = (float(*)[128])(dsm + 23808);
    float (*s_e)[128]       = (float(*)[128])(dsm + 25856);
    float (*s_a)[128]       = (float(*)[128])(dsm + 27904);
    float (*s_w)[128]       = (float(*)[128])(dsm + 29952);
    float (*s_racc)[4][128] = (float(*)[4][128])(dsm + 32000);
    float (*s_read)[128]    = (float(*)[128])(dsm + 40192);
    float* s_beta           = (float*)(dsm + 42240);
    int*   s_len            = (int*)(dsm + 42256);
    int*   s_dst            = (int*)(dsm + 42272);
    __half* s_M             = (__half*)(dsm + 42304);          // [4][128][128]

    const int tid = threadIdx.x;
    const int lane = tid & 31;
    const int warp = tid >> 5;
    const int gid = lane >> 2, tig = lane & 3;
    const int b0blk = blockIdx.x * 4;

    // ---- active lengths ----
    if (warp < 4) {
        int e = warp, cnt = 0;
        for (int t = lane; t < TN; t += 32) cnt += (batch_sizes[t] > (b0blk + e)) ? 1 : 0;
        #pragma unroll
        for (int s = 16; s; s >>= 1) cnt += __shfl_xor_sync(0xffffffffu, cnt, s);
        if (lane == 0) s_len[e] = cnt;
    }
    // ---- init M in SMEM ----
    for (int i = tid; i < (MEMN * WORDN) / 2; i += 512) {
        float2 f = ((const float2*)M0)[i];
        __half2 h = __floats2half2_rn(f.x, f.y);
        #pragma unroll
        for (int e = 0; e < 4; e++)
            ((__half2*)s_M)[e * ((MEMN * WORDN) / 2) + i] = h;
    }
    for (int i = tid; i < 8 * STRX; i += 512) s_inh[i] = __float2half(0.0f);
    for (int i = tid; i < 8 * STRH; i += 512) s_hHf[i] = __float2half(0.0f);

    // ---- per-lane constants ----
    const int mpos = warp;
    const int j0 = mpos * 16 + gid, j1 = j0 + 8;
    const float bR0 = b_ih[j0] + b_hh[j0],           bR1 = b_ih[j1] + b_hh[j1];
    const float bZ0 = b_ih[256 + j0] + b_hh[256 + j0], bZ1 = b_ih[256 + j1] + b_hh[256 + j1];
    const float bNi0 = b_ih[512 + j0],               bNi1 = b_ih[512 + j1];
    const float bNh0 = b_hh[512 + j0],               bNh1 = b_hh[512 + j1];
    float bHv[8];
    if (warp < 8) {
        #pragma unroll
        for (int tt = 0; tt < 4; tt++) {
            int o = (warp * 4 + tt) * 16 + gid;
            #pragma unroll
            for (int rr = 0; rr < 2; rr++) {
                int oo = o + rr * 8;
                float v = (oo < 128) ? b_key[oo]
                        : (oo < 256) ? b_erase[oo - 128]
                        : (oo < 384) ? b_add[oo - 256]
                        : ((oo == 384) ? b_beta[0] : 0.0f);
                bHv[2 * tt + rr] = v;
            }
        }
    }
    const int e0 = 2 * tig, e1 = e0 + 1;           // valid for tig<2
    float hreg[4] = {0.f, 0.f, 0.f, 0.f};

    // module roles (R8): 4 warps per elem
    const int me = (warp < 8) ? (warp >> 1) : ((warp >> 1) - 4);
    const int qt = (warp < 8) ? (warp & 1) : (2 + (warp & 1));

    // ---- x prefetch ----
    const int xe = tid >> 6, xd = tid & 63;
    float xreg = 0.f;
    if (tid < 256) xreg = data[((size_t)0 * BN + (b0blk + xe)) * DINN + xd];
    __syncthreads();

    int Le0 = 0, Le1 = 0;
    if (tig < 2) { Le0 = s_len[e0]; Le1 = s_len[e1]; }
    const int Tmax = max(max(s_len[0], s_len[1]), max(s_len[2], s_len[3]));

    if (tid < 256) {
        s_inh[xe * STRX + xd] = __float2half(xreg);
        xreg = data[((size_t)1 * BN + (b0blk + xe)) * DINN + xd];
    }
    __syncthreads();
    if (warp >= 8) pipe_mma(warp, lane, gid, tig, s_inh, s_hHf, red);
    __syncthreads();

    for (int t = 0; t < Tmax; ++t) {
        // ======== SERIAL: gi_read mma (k-tiles 4..11), all 16 warps ========
        float Cr[4] = {0, 0, 0, 0}, Cz[4] = {0, 0, 0, 0}, Cni[4] = {0, 0, 0, 0};
        {
            const uint4* A = (const uint4*)gA;
            #pragma unroll 4
            for (int kt = 4; kt < 12; ++kt) {
                uint32_t b0 = *(const uint32_t*)(s_inh + gid * STRX + kt * 16 + 2 * tig);
                uint32_t b1 = *(const uint32_t*)(s_inh + gid * STRX + kt * 16 + 2 * tig + 8);
                uint4 ar = __ldg(&A[(size_t)((mpos * 3 + 0) * 28 + kt) * 32 + lane]);
                uint4 az = __ldg(&A[(size_t)((mpos * 3 + 1) * 28 + kt) * 32 + lane]);
                uint4 an = __ldg(&A[(size_t)((mpos * 3 + 2) * 28 + kt) * 32 + lane]);
                MMA(Cr, ar, b0, b1);
                MMA(Cz, az, b0, b1);
                MMA(Cni, an, b0, b1);
            }
        }
        // ---- gates (in-register h state) ----
        if (tig < 2) {
            #pragma unroll
            for (int c = 0; c < 4; ++c) {
                int jj = (c & 2) ? j1 : j0;
                int ee = (c & 1) ? e1 : e0;
                int Lc = (c & 1) ? Le1 : Le0;
                float rp = Cr[c]  + red[(0 * 256 + jj) * 4 + ee] + ((c & 2) ? bR1 : bR0);
                float zp = Cz[c]  + red[(1 * 256 + jj) * 4 + ee] + ((c & 2) ? bZ1 : bZ0);
                float np = Cni[c] + red[(2 * 256 + jj) * 4 + ee] + ((c & 2) ? bNi1 : bNi0);
                float nh = red[(3 * 256 + jj) * 4 + ee] + ((c & 2) ? bNh1 : bNh0);
                float r = sigf(rp);
                float z = sigf(zp);
                float n = tanhf_fast(np + r * nh);
                float h = (1.0f - z) * n + z * hreg[c];
                if (t < Lc) hreg[c] = h;
                s_hHf[ee * STRH + jj] = __float2half(hreg[c]);
            }
        }
        // x_{t+1} -> smem, prefetch x_{t+2}
        if (tid < 256) {
            s_inh[xe * STRX + xd] = __float2half(xreg);
            int tn = min(t + 2, TN - 1);
            xreg = data[((size_t)tn * BN + (b0blk + xe)) * DINN + xd];
        }
        __syncthreads();   // B1

        // ======== PARALLEL ========
        if (warp >= 8) {
            pipe_mma(warp, lane, gid, tig, s_inh, s_hHf, red);
        } else {
            // head mma: 4 m-tiles x 16 k-tiles
            float CH[4][4];
            #pragma unroll
            for (int tt = 0; tt < 4; tt++)
                #pragma unroll
                for (int c = 0; c < 4; c++) CH[tt][c] = 0.0f;
            const uint4* AH = (const uint4*)gAH;
            #pragma unroll 2
            for (int kt = 0; kt < 16; ++kt) {
                uint32_t b0 = *(const uint32_t*)(s_hHf + gid * STRH + kt * 16 + 2 * tig);
                uint32_t b1 = *(const uint32_t*)(s_hHf + gid * STRH + kt * 16 + 2 * tig + 8);
                #pragma unroll
                for (int tt = 0; tt < 4; tt++) {
                    uint4 a = __ldg(&AH[(size_t)((warp * 4 + tt) * 16 + kt) * 32 + lane]);
                    MMA(CH[tt], a, b0, b1);
                }
            }
            if (tig < 2) {
                #pragma unroll
                for (int tt = 0; tt < 4; tt++) {
                    int obase = (warp * 4 + tt) * 16 + gid;
                    #pragma unroll
                    for (int c = 0; c < 4; c++) {
                        int o = obase + ((c & 2) ? 8 : 0);
                        int ee = (c & 1) ? e1 : e0;
                        float v = CH[tt][c] + bHv[2 * tt + ((c >> 1) & 1)];
                        if (o < 128)       s_key[ee][o] = tanhf_fast(v);
                        else if (o < 256)  s_e[ee][o - 128] = sigf(v);
                        else if (o < 384)  s_a[ee][o - 256] = v;
                        else if (o == 384) s_beta[ee] = softplusf(v);
                    }
                }
            }
            BARN(5, 256);
        }

        // ======== MEMORY MODULE: 4 warps/elem (joined) ========
        {
            const int e = me;
            if (t < s_len[e]) {
                BARN(1 + e, 128);
                const __half* Me = s_M + e * (MEMN * WORDN);
                {
                    int rl = lane >> 3;
                    int cc = (lane & 7) * 16;
                    float2 kx[8];
                    #pragma unroll
                    for (int i = 0; i < 8; i++)
                        kx[i] = make_float2(s_key[e][cc + 2 * i], s_key[e][cc + 2 * i + 1]);
                    #pragma unroll 4
                    for (int mb = qt * 32; mb < qt * 32 + 32; mb += 4) {
                        int m = mb + rl;
                        const uint4* Mr = (const uint4*)(Me + m * WORDN + cc);
                        uint4 u0 = Mr[0];
                        uint4 u1 = Mr[1];
                        const __half2* p0 = (const __half2*)&u0;
                        const __half2* p1 = (const __half2*)&u1;
                        float2 d2 = make_float2(0.f, 0.f), n2 = make_float2(0.f, 0.f);
                        #pragma unroll
                        for (int q = 0; q < 4; q++) {
                            float2 f0 = __half22float2(p0[q]);
                            float2 f1 = __half22float2(p1[q]);
                            ffma2(d2, f0, kx[q]);
                            ffma2(n2, f0, f0);
                            ffma2(d2, f1, kx[4 + q]);
                            ffma2(n2, f1, f1);
                        }
                        float dot = d2.x + d2.y, nrm = n2.x + n2.y;
                        #pragma unroll
                        for (int s = 1; s < 8; s <<= 1) {
                            dot += __shfl_xor_sync(0xffffffffu, dot, s);
                            nrm += __shfl_xor_sync(0xffffffffu, nrm, s);
                        }
                        if ((lane & 7) == 0) s_w[e][m] = __fdividef(dot, sqrt_fast(nrm) + EPSF);
                    }
                }
                BARN(1 + e, 128);
                if (qt == 0) {
                    float q0 = s_key[e][lane];
                    float q1 = s_key[e][lane + 32];
                    float q2 = s_key[e][lane + 64];
                    float q3 = s_key[e][lane + 96];
                    float ss = q0 * q0 + q1 * q1 + q2 * q2 + q3 * q3;
                    #pragma unroll
                    for (int s = 16; s; s >>= 1) ss += __shfl_xor_sync(0xffffffffu, ss, s);
                    float scale = __fdividef(s_beta[e], sqrt_fast(ss) + EPSF);
                    float v0 = scale * s_w[e][lane];
                    float v1 = scale * s_w[e][lane + 32];
                    float v2 = scale * s_w[e][lane + 64];
                    float v3 = scale * s_w[e][lane + 96];
                    float mx = fmaxf(fmaxf(v0, v1), fmaxf(v2, v3));
                    #pragma unroll
                    for (int s = 16; s; s >>= 1) mx = fmaxf(mx, __shfl_xor_sync(0xffffffffu, mx, s));
                    v0 = __expf(v0 - mx); v1 = __expf(v1 - mx);
                    v2 = __expf(v2 - mx); v3 = __expf(v3 - mx);
                    float sum = v0 + v1 + v2 + v3;
                    #pragma unroll
                    for (int s = 16; s; s >>= 1) sum += __shfl_xor_sync(0xffffffffu, sum, s);
                    float inv = __fdividef(1.0f, sum);
                    s_w[e][lane] = v0 * inv;
                    s_w[e][lane + 32] = v1 * inv;
                    s_w[e][lane + 64] = v2 * inv;
                    s_w[e][lane + 96] = v3 * inv;
                }
                BARN(1 + e, 128);
                {
                    __half* Mw = s_M + e * (MEMN * WORDN) + lane * 4;
                    float4 e4 = *(const float4*)&s_e[e][lane * 4];
                    float4 a4 = *(const float4*)&s_a[e][lane * 4];
                    float2 en01 = make_float2(-e4.x, -e4.y), en23 = make_float2(-e4.z, -e4.w);
                    float2 a01 = make_float2(a4.x, a4.y),    a23 = make_float2(a4.z, a4.w);
                    float2 r01 = make_float2(0.f, 0.f), r23 = make_float2(0.f, 0.f);
                    #pragma unroll 8
                    for (int m = qt * 32; m < qt * 32 + 32; ++m) {
                        float wm = s_w[e][m];
                        float2 wm2 = dup2(wm);
                        uint2 u = *(uint2*)(Mw + m * WORDN);
                        __half2* hp = (__half2*)&u;
                        float2 m01 = __half22float2(hp[0]);
                        float2 m23 = __half22float2(hp[1]);
                        ffma2(r01, wm2, m01);
                        ffma2(r23, wm2, m23);
                        float2 f01 = make_float2(1.f, 1.f), f23 = make_float2(1.f, 1.f);
                        ffma2(f01, wm2, en01);
                        ffma2(f23, wm2, en23);
                        float2 w01 = make_float2(0.f, 0.f), w23 = make_float2(0.f, 0.f);
                        ffma2(w01, wm2, a01);
                        ffma2(w23, wm2, a23);
                        ffma2(w01, m01, f01);
                        ffma2(w23, m23, f23);
                        hp[0] = __floats2half2_rn(w01.x, w01.y);
                        hp[1] = __floats2half2_rn(w23.x, w23.y);
                        *(uint2*)(Mw + m * WORDN) = u;
                    }
                    *(float4*)&s_racc[e][qt][lane * 4] = make_float4(r01.x, r01.y, r23.x, r23.y);
                }
                BARN(1 + e, 128);
                {
                    int w = qt * 32 + lane;
                    float s = (s_racc[e][0][w] + s_racc[e][1][w])
                            + (s_racc[e][2][w] + s_racc[e][3][w]);
                    s_read[e][w] = s;
                    s_inh[e * STRX + 64 + w] = __float2half(s);
                }
            }
        }
        __syncthreads();   // B4
    }

    // ---- epilogue ----
    for (int q = tid; q < BN; q += 512) {
        int u = unsort_idxs[q];
        if (u >= b0blk && u < b0blk + 4) s_dst[u - b0blk] = q;
    }
    __syncthreads();
    if (tig < 2) {
        #pragma unroll
        for (int c = 0; c < 4; ++c) {
            int jj = (c & 2) ? j1 : j0;
            int ee = (c & 1) ? e1 : e0;
            out[(size_t)s_dst[ee] * CTRLN + jj] = hreg[c];
        }
    }
    {
        int e = tid >> 7, w = tid & 127;
        if (tid < 512)
            out[(size_t)BN * CTRLN + (size_t)s_dst[e] * WORDN + w] = s_read[e][w];
    }
}

// ---------------- launch ----------------
extern "C" void kernel_launch(void* const* d_in, const int* in_sizes, int n_in,
                              void* d_out, int out_size) {
    const float* data        = (const float*)d_in[0];
    const int*   batch_sizes = (const int*)d_in[1];
    const int*   unsort      = (const int*)d_in[2];
    const float* W_ih        = (const float*)d_in[3];
    const float* b_ih        = (const float*)d_in[4];
    const float* W_hh        = (const float*)d_in[5];
    const float* b_hh        = (const float*)d_in[6];
    const float* W_key       = (const float*)d_in[7];
    const float* b_key       = (const float*)d_in[8];
    const float* W_beta      = (const float*)d_in[9];
    const float* b_beta      = (const float*)d_in[10];
    const float* W_erase     = (const float*)d_in[11];
    const float* b_erase     = (const float*)d_in[12];
    const float* W_add       = (const float*)d_in[13];
    const float* b_add       = (const float*)d_in[14];
    const float* M0          = (const float*)d_in[15];

    cudaFuncSetAttribute(ntm_main, cudaFuncAttributeMaxDynamicSharedMemorySize, SMEM_TOTAL);
    ntm_prep<<<256, 256>>>(W_ih, W_hh, W_key, W_beta, W_erase, W_add);
    ntm_main<<<128, 512, SMEM_TOTAL>>>(data, batch_sizes, unsort,
                                       b_ih, b_hh, b_key, b_beta, b_erase, b_add,
                                       M0, (float*)d_out);
}

// round 12
// speedup vs baseline: 1.4825x; 1.1137x over previous
#include <cuda_runtime.h>
#include <cuda_fp16.h>
#include <stdint.h>
#include <math.h>

#define CTRLN 256
#define WORDN 128
#define MEMN  128
#define DINN  64
#define BN    512
#define TN    512
#define EPSF  1e-6f

#define STRX 200   // s_inh row stride (halves), bank-spread
#define STRH 264   // s_hHf row stride (halves)

// fragment-major fp16 weights
__device__ __half gA[16 * 3 * 28 * 256];   // GRU: [mpos][gate][ktile] x 256 halves/tile
__device__ __half gAH[32 * 16 * 256];      // head: [htile][ktile] x 256 halves/tile

// ---------------- helpers ----------------
__device__ __forceinline__ void ffma2(float2 &d, float2 a, float2 b) {
    unsigned long long &du = reinterpret_cast<unsigned long long &>(d);
    unsigned long long au = reinterpret_cast<unsigned long long &>(a);
    unsigned long long bu = reinterpret_cast<unsigned long long &>(b);
    asm("fma.rn.f32x2 %0, %1, %2, %0;" : "+l"(du) : "l"(au), "l"(bu));
}
__device__ __forceinline__ float2 dup2(float a) { return make_float2(a, a); }
__device__ __forceinline__ float sigf(float x) {
    return __fdividef(1.0f, 1.0f + __expf(-x));
}
__device__ __forceinline__ float tanhf_fast(float x) {
    float ax = fabsf(x);
    float t = __expf(-2.0f * ax);
    float r = (1.0f - t) * __fdividef(1.0f, 1.0f + t);
    return copysignf(r, x);
}
__device__ __forceinline__ float softplusf(float x) {
    return fmaxf(x, 0.0f) + log1pf(__expf(-fabsf(x)));
}
__device__ __forceinline__ float sqrt_fast(float x) {
    float xs = x + 1e-30f;
    return xs * rsqrtf(xs);
}
#define BARN(id, cnt) asm volatile("bar.sync %0, %1;" :: "r"(id), "r"(cnt) : "memory")

#define MMA(C, A, B0, B1) \
    asm volatile("mma.sync.aligned.m16n8k16.row.col.f32.f16.f16.f32 " \
        "{%0,%1,%2,%3},{%4,%5,%6,%7},{%8,%9},{%0,%1,%2,%3};" \
        : "+f"((C)[0]), "+f"((C)[1]), "+f"((C)[2]), "+f"((C)[3]) \
        : "r"((A).x), "r"((A).y), "r"((A).z), "r"((A).w), "r"(B0), "r"(B1))

// ---------------- K0: repack weights to fragment-major fp16 ----------------
__global__ void ntm_prep(const float* __restrict__ W_ih, const float* __restrict__ W_hh,
                         const float* __restrict__ W_key, const float* __restrict__ W_beta,
                         const float* __restrict__ W_erase, const float* __restrict__ W_add) {
    int stride = gridDim.x * blockDim.x;
    int idx0 = blockIdx.x * blockDim.x + threadIdx.x;
    // GRU tiles
    for (int i = idx0; i < 16 * 3 * 28 * 256; i += stride) {
        int tile = i >> 8, rem = i & 255;
        int lane = rem >> 3, p = rem & 7;
        int gid = lane >> 2, tig = lane & 3;
        int reg = p >> 1, w = p & 1;
        int r = gid + (reg & 1) * 8;
        int k = 2 * tig + (reg >> 1) * 8 + w;
        int mt = tile / 84, g = (tile / 28) % 3, kt = tile % 28;
        int o = g * 256 + mt * 16 + r;
        float v = (kt < 12) ? W_ih[o * 192 + kt * 16 + k]
                            : W_hh[o * 256 + (kt - 12) * 16 + k];
        gA[i] = __float2half(v);
    }
    // head tiles
    for (int i = idx0; i < 32 * 16 * 256; i += stride) {
        int tile = i >> 8, rem = i & 255;
        int lane = rem >> 3, p = rem & 7;
        int gid = lane >> 2, tig = lane & 3;
        int reg = p >> 1, w = p & 1;
        int r = gid + (reg & 1) * 8;
        int k = 2 * tig + (reg >> 1) * 8 + w;
        int ht = tile / 16, kt = tile % 16;
        int o = ht * 16 + r;
        int kk = kt * 16 + k;
        float v = 0.0f;
        if (o < 128)       v = W_key[o * 256 + kk];
        else if (o < 256)  v = W_erase[(o - 128) * 256 + kk];
        else if (o < 384)  v = W_add[(o - 256) * 256 + kk];
        else if (o == 384) v = W_beta[kk];
        gAH[i] = __float2half(v);
    }
}

// ---------------- pipelined mma: gh(h) + gi_x(x) for 2 m-positions ----------------
__device__ __forceinline__ void pipe_mma(int warp, int lane, int gid, int tig,
                                         const __half* __restrict__ s_inh,
                                         const __half* __restrict__ s_hHf,
                                         float* __restrict__ red) {
    const int mp0 = (warp - 8) * 2;
    float C[2][4][4];
    #pragma unroll
    for (int m = 0; m < 2; m++)
        #pragma unroll
        for (int a = 0; a < 4; a++)
            #pragma unroll
            for (int c = 0; c < 4; c++) C[m][a][c] = 0.0f;
    const uint4* A = (const uint4*)gA;
    // gi_x: k-tiles 0..3 (x rows of s_inh)
    #pragma unroll 2
    for (int kt = 0; kt < 4; ++kt) {
        uint32_t b0 = *(const uint32_t*)(s_inh + gid * STRX + kt * 16 + 2 * tig);
        uint32_t b1 = *(const uint32_t*)(s_inh + gid * STRX + kt * 16 + 2 * tig + 8);
        #pragma unroll
        for (int m = 0; m < 2; m++) {
            int mp = mp0 + m;
            uint4 ar = __ldg(&A[(size_t)((mp * 3 + 0) * 28 + kt) * 32 + lane]);
            uint4 az = __ldg(&A[(size_t)((mp * 3 + 1) * 28 + kt) * 32 + lane]);
            uint4 an = __ldg(&A[(size_t)((mp * 3 + 2) * 28 + kt) * 32 + lane]);
            MMA(C[m][0], ar, b0, b1);
            MMA(C[m][1], az, b0, b1);
            MMA(C[m][2], an, b0, b1);
        }
    }
    // gh: k-tiles 0..15 over s_hHf (n-gate -> nh accumulator)
    #pragma unroll 2
    for (int kt = 0; kt < 16; ++kt) {
        uint32_t b0 = *(const uint32_t*)(s_hHf + gid * STRH + kt * 16 + 2 * tig);
        uint32_t b1 = *(const uint32_t*)(s_hHf + gid * STRH + kt * 16 + 2 * tig + 8);
        #pragma unroll
        for (int m = 0; m < 2; m++) {
            int mp = mp0 + m;
            uint4 ar = __ldg(&A[(size_t)((mp * 3 + 0) * 28 + 12 + kt) * 32 + lane]);
            uint4 az = __ldg(&A[(size_t)((mp * 3 + 1) * 28 + 12 + kt) * 32 + lane]);
            uint4 an = __ldg(&A[(size_t)((mp * 3 + 2) * 28 + 12 + kt) * 32 + lane]);
            MMA(C[m][0], ar, b0, b1);
            MMA(C[m][1], az, b0, b1);
            MMA(C[m][3], an, b0, b1);
        }
    }
    if (tig < 2) {
        int e0 = 2 * tig;
        #pragma unroll
        for (int m = 0; m < 2; m++) {
            int j0 = (mp0 + m) * 16 + gid;
            #pragma unroll
            for (int a = 0; a < 4; a++) {
                *(float2*)&red[(a * 256 + j0) * 4 + e0] = make_float2(C[m][a][0], C[m][a][1]);
                *(float2*)&red[(a * 256 + j0 + 8) * 4 + e0] = make_float2(C[m][a][2], C[m][a][3]);
            }
        }
    }
}

#define SMEM_TOTAL (42304 + 4 * MEMN * WORDN * 2)   // 173376 bytes

// ---------------- K1: persistent tensor-core kernel (un-joined module) ----------------
__global__ __launch_bounds__(512, 1)
void ntm_main(const float* __restrict__ data, const int* __restrict__ batch_sizes,
              const int* __restrict__ unsort_idxs,
              const float* __restrict__ b_ih, const float* __restrict__ b_hh,
              const float* __restrict__ b_key, const float* __restrict__ b_beta,
              const float* __restrict__ b_erase, const float* __restrict__ b_add,
              const float* __restrict__ M0, float* __restrict__ out) {
    extern __shared__ __align__(16) unsigned char dsm[];
    __half* s_inh           = (__half*)(dsm);                  // [8][STRX]: 0..63 x, 64..191 read
    __half* s_hHf           = (__half*)(dsm + 3200);           // [8][STRH] fp16 h
    float*  red             = (float*)(dsm + 7424);            // [4 acc][256 j][4 e]
    float (*s_key)[128]     = (float(*)[128])(dsm + 23808);
    float (*s_e)[128]       = (float(*)[128])(dsm + 25856);
    float (*s_a)[128]       = (float(*)[128])(dsm + 27904);
    float (*s_w)[128]       = (float(*)[128])(dsm + 29952);
    float (*s_racc)[2][128] = (float(*)[2][128])(dsm + 32000); // [4][2][128]
    float (*s_read)[128]    = (float(*)[128])(dsm + 40192);
    float* s_beta           = (float*)(dsm + 42240);
    int*   s_len            = (int*)(dsm + 42256);
    int*   s_dst            = (int*)(dsm + 42272);
    __half* s_M             = (__half*)(dsm + 42304);          // [4][128][128]

    const int tid = threadIdx.x;
    const int lane = tid & 31;
    const int warp = tid >> 5;
    const int gid = lane >> 2, tig = lane & 3;
    const int b0blk = blockIdx.x * 4;

    // ---- active lengths ----
    if (warp < 4) {
        int e = warp, cnt = 0;
        for (int t = lane; t < TN; t += 32) cnt += (batch_sizes[t] > (b0blk + e)) ? 1 : 0;
        #pragma unroll
        for (int s = 16; s; s >>= 1) cnt += __shfl_xor_sync(0xffffffffu, cnt, s);
        if (lane == 0) s_len[e] = cnt;
    }
    // ---- init M in SMEM ----
    for (int i = tid; i < (MEMN * WORDN) / 2; i += 512) {
        float2 f = ((const float2*)M0)[i];
        __half2 h = __floats2half2_rn(f.x, f.y);
        #pragma unroll
        for (int e = 0; e < 4; e++)
            ((__half2*)s_M)[e * ((MEMN * WORDN) / 2) + i] = h;
    }
    for (int i = tid; i < 8 * STRX; i += 512) s_inh[i] = __float2half(0.0f);
    for (int i = tid; i < 8 * STRH; i += 512) s_hHf[i] = __float2half(0.0f);

    // ---- per-lane constants ----
    const int mpos = warp;
    const int j0 = mpos * 16 + gid, j1 = j0 + 8;
    const float bR0 = b_ih[j0] + b_hh[j0],             bR1 = b_ih[j1] + b_hh[j1];
    const float bZ0 = b_ih[256 + j0] + b_hh[256 + j0], bZ1 = b_ih[256 + j1] + b_hh[256 + j1];
    const float bNi0 = b_ih[512 + j0],                 bNi1 = b_ih[512 + j1];
    const float bNh0 = b_hh[512 + j0],                 bNh1 = b_hh[512 + j1];
    float bHv[8];
    if (warp < 8) {
        #pragma unroll
        for (int tt = 0; tt < 4; tt++) {
            int o = (warp * 4 + tt) * 16 + gid;
            #pragma unroll
            for (int rr = 0; rr < 2; rr++) {
                int oo = o + rr * 8;
                float v = (oo < 128) ? b_key[oo]
                        : (oo < 256) ? b_erase[oo - 128]
                        : (oo < 384) ? b_add[oo - 256]
                        : ((oo == 384) ? b_beta[0] : 0.0f);
                bHv[2 * tt + rr] = v;
            }
        }
    }
    const int e0 = 2 * tig, e1 = e0 + 1;           // valid for tig<2
    float hreg[4] = {0.f, 0.f, 0.f, 0.f};

    // module roles: MEM warps 0-7 only, 2 warps/elem
    const int me = warp >> 1;                       // valid for warps 0-7
    const int half = warp & 1;

    // ---- x prefetch ----
    const int xe = tid >> 6, xd = tid & 63;
    float xreg = 0.f;
    if (tid < 256) xreg = data[((size_t)0 * BN + (b0blk + xe)) * DINN + xd];
    __syncthreads();

    int Le0 = 0, Le1 = 0;
    if (tig < 2) { Le0 = s_len[e0]; Le1 = s_len[e1]; }
    const int Tmax = max(max(s_len[0], s_len[1]), max(s_len[2], s_len[3]));

    if (tid < 256) {
        s_inh[xe * STRX + xd] = __float2half(xreg);
        xreg = data[((size_t)1 * BN + (b0blk + xe)) * DINN + xd];
    }
    __syncthreads();
    if (warp >= 8) pipe_mma(warp, lane, gid, tig, s_inh, s_hHf, red);
    __syncthreads();

    for (int t = 0; t < Tmax; ++t) {
        // ======== SERIAL: gi_read mma (k-tiles 4..11), all 16 warps ========
        float Cr[4] = {0, 0, 0, 0}, Cz[4] = {0, 0, 0, 0}, Cni[4] = {0, 0, 0, 0};
        {
            const uint4* A = (const uint4*)gA;
            #pragma unroll 4
            for (int kt = 4; kt < 12; ++kt) {
                uint32_t b0 = *(const uint32_t*)(s_inh + gid * STRX + kt * 16 + 2 * tig);
                uint32_t b1 = *(const uint32_t*)(s_inh + gid * STRX + kt * 16 + 2 * tig + 8);
                uint4 ar = __ldg(&A[(size_t)((mpos * 3 + 0) * 28 + kt) * 32 + lane]);
                uint4 az = __ldg(&A[(size_t)((mpos * 3 + 1) * 28 + kt) * 32 + lane]);
                uint4 an = __ldg(&A[(size_t)((mpos * 3 + 2) * 28 + kt) * 32 + lane]);
                MMA(Cr, ar, b0, b1);
                MMA(Cz, az, b0, b1);
                MMA(Cni, an, b0, b1);
            }
        }
        // ---- gates (in-register h state) ----
        if (tig < 2) {
            #pragma unroll
            for (int c = 0; c < 4; ++c) {
                int jj = (c & 2) ? j1 : j0;
                int ee = (c & 1) ? e1 : e0;
                int Lc = (c & 1) ? Le1 : Le0;
                float rp = Cr[c]  + red[(0 * 256 + jj) * 4 + ee] + ((c & 2) ? bR1 : bR0);
                float zp = Cz[c]  + red[(1 * 256 + jj) * 4 + ee] + ((c & 2) ? bZ1 : bZ0);
                float np = Cni[c] + red[(2 * 256 + jj) * 4 + ee] + ((c & 2) ? bNi1 : bNi0);
                float nh = red[(3 * 256 + jj) * 4 + ee] + ((c & 2) ? bNh1 : bNh0);
                float r = sigf(rp);
                float z = sigf(zp);
                float n = tanhf_fast(np + r * nh);
                float h = (1.0f - z) * n + z * hreg[c];
                if (t < Lc) hreg[c] = h;
                s_hHf[ee * STRH + jj] = __float2half(hreg[c]);
            }
        }
        // x_{t+1} -> smem, prefetch x_{t+2}
        if (tid < 256) {
            s_inh[xe * STRX + xd] = __float2half(xreg);
            int tn = min(t + 2, TN - 1);
            xreg = data[((size_t)tn * BN + (b0blk + xe)) * DINN + xd];
        }
        __syncthreads();   // B1

        // ======== PARALLEL ========
        if (warp >= 8) {
            // pipe warps: next-step partials only; never touch module barriers
            pipe_mma(warp, lane, gid, tig, s_inh, s_hHf, red);
        } else {
            // ---- head mma: 4 m-tiles x 16 k-tiles ----
            float CH[4][4];
            #pragma unroll
            for (int tt = 0; tt < 4; tt++)
                #pragma unroll
                for (int c = 0; c < 4; c++) CH[tt][c] = 0.0f;
            const uint4* AH = (const uint4*)gAH;
            #pragma unroll 2
            for (int kt = 0; kt < 16; ++kt) {
                uint32_t b0 = *(const uint32_t*)(s_hHf + gid * STRH + kt * 16 + 2 * tig);
                uint32_t b1 = *(const uint32_t*)(s_hHf + gid * STRH + kt * 16 + 2 * tig + 8);
                #pragma unroll
                for (int tt = 0; tt < 4; tt++) {
                    uint4 a = __ldg(&AH[(size_t)((warp * 4 + tt) * 16 + kt) * 32 + lane]);
                    MMA(CH[tt], a, b0, b1);
                }
            }
            if (tig < 2) {
                #pragma unroll
                for (int tt = 0; tt < 4; tt++) {
                    int obase = (warp * 4 + tt) * 16 + gid;
                    #pragma unroll
                    for (int c = 0; c < 4; c++) {
                        int o = obase + ((c & 2) ? 8 : 0);
                        int ee = (c & 1) ? e1 : e0;
                        float v = CH[tt][c] + bHv[2 * tt + ((c >> 1) & 1)];
                        if (o < 128)       s_key[ee][o] = tanhf_fast(v);
                        else if (o < 256)  s_e[ee][o - 128] = sigf(v);
                        else if (o < 384)  s_a[ee][o - 256] = v;
                        else if (o == 384) s_beta[ee] = softplusf(v);
                    }
                }
            }
            BARN(5, 256);   // head outputs visible to MEM warps

            // ---- memory module: 2 warps/elem (warps 0-7 only) ----
            const int e = me;
            if (t < s_len[e]) {
                const __half* Me = s_M + e * (MEMN * WORDN);
                // pass 1: dot(M, k_raw)/(||M||+eps), 64 rows/warp
                {
                    int rl = lane >> 3;
                    int cc = (lane & 7) * 16;
                    float2 kx[8];
                    #pragma unroll
                    for (int i = 0; i < 8; i++)
                        kx[i] = make_float2(s_key[e][cc + 2 * i], s_key[e][cc + 2 * i + 1]);
                    #pragma unroll 4
                    for (int mb = half * 64; mb < half * 64 + 64; mb += 4) {
                        int m = mb + rl;
                        const uint4* Mr = (const uint4*)(Me + m * WORDN + cc);
                        uint4 u0 = Mr[0];
                        uint4 u1 = Mr[1];
                        const __half2* p0 = (const __half2*)&u0;
                        const __half2* p1 = (const __half2*)&u1;
                        float2 d2 = make_float2(0.f, 0.f), n2 = make_float2(0.f, 0.f);
                        #pragma unroll
                        for (int q = 0; q < 4; q++) {
                            float2 f0 = __half22float2(p0[q]);
                            float2 f1 = __half22float2(p1[q]);
                            ffma2(d2, f0, kx[q]);
                            ffma2(n2, f0, f0);
                            ffma2(d2, f1, kx[4 + q]);
                            ffma2(n2, f1, f1);
                        }
                        float dot = d2.x + d2.y, nrm = n2.x + n2.y;
                        #pragma unroll
                        for (int s = 1; s < 8; s <<= 1) {
                            dot += __shfl_xor_sync(0xffffffffu, dot, s);
                            nrm += __shfl_xor_sync(0xffffffffu, nrm, s);
                        }
                        if ((lane & 7) == 0) s_w[e][m] = __fdividef(dot, sqrt_fast(nrm) + EPSF);
                    }
                }
                BARN(1 + e, 64);
                // softmax (half==0 warp): scale = beta / (||k||+eps)
                if (half == 0) {
                    float q0 = s_key[e][lane];
                    float q1 = s_key[e][lane + 32];
                    float q2 = s_key[e][lane + 64];
                    float q3 = s_key[e][lane + 96];
                    float ss = q0 * q0 + q1 * q1 + q2 * q2 + q3 * q3;
                    #pragma unroll
                    for (int s = 16; s; s >>= 1) ss += __shfl_xor_sync(0xffffffffu, ss, s);
                    float scale = __fdividef(s_beta[e], sqrt_fast(ss) + EPSF);
                    float v0 = scale * s_w[e][lane];
                    float v1 = scale * s_w[e][lane + 32];
                    float v2 = scale * s_w[e][lane + 64];
                    float v3 = scale * s_w[e][lane + 96];
                    float mx = fmaxf(fmaxf(v0, v1), fmaxf(v2, v3));
                    #pragma unroll
                    for (int s = 16; s; s >>= 1) mx = fmaxf(mx, __shfl_xor_sync(0xffffffffu, mx, s));
                    v0 = __expf(v0 - mx); v1 = __expf(v1 - mx);
                    v2 = __expf(v2 - mx); v3 = __expf(v3 - mx);
                    float sum = v0 + v1 + v2 + v3;
                    #pragma unroll
                    for (int s = 16; s; s >>= 1) sum += __shfl_xor_sync(0xffffffffu, sum, s);
                    float inv = __fdividef(1.0f, sum);
                    s_w[e][lane] = v0 * inv;
                    s_w[e][lane + 32] = v1 * inv;
                    s_w[e][lane + 64] = v2 * inv;
                    s_w[e][lane + 96] = v3 * inv;
                }
                BARN(1 + e, 64);
                // pass 2: fused read + M update, 64 rows/warp
                {
                    __half* Mw = s_M + e * (MEMN * WORDN) + lane * 4;
                    float4 e4 = *(const float4*)&s_e[e][lane * 4];
                    float4 a4 = *(const float4*)&s_a[e][lane * 4];
                    float2 en01 = make_float2(-e4.x, -e4.y), en23 = make_float2(-e4.z, -e4.w);
                    float2 a01 = make_float2(a4.x, a4.y),    a23 = make_float2(a4.z, a4.w);
                    float2 r01 = make_float2(0.f, 0.f), r23 = make_float2(0.f, 0.f);
                    #pragma unroll 8
                    for (int m = half * 64; m < half * 64 + 64; ++m) {
                        float wm = s_w[e][m];
                        float2 wm2 = dup2(wm);
                        uint2 u = *(uint2*)(Mw + m * WORDN);
                        __half2* hp = (__half2*)&u;
                        float2 m01 = __half22float2(hp[0]);
                        float2 m23 = __half22float2(hp[1]);
                        ffma2(r01, wm2, m01);
                        ffma2(r23, wm2, m23);
                        float2 f01 = make_float2(1.f, 1.f), f23 = make_float2(1.f, 1.f);
                        ffma2(f01, wm2, en01);
                        ffma2(f23, wm2, en23);
                        float2 w01 = make_float2(0.f, 0.f), w23 = make_float2(0.f, 0.f);
                        ffma2(w01, wm2, a01);
                        ffma2(w23, wm2, a23);
                        ffma2(w01, m01, f01);
                        ffma2(w23, m23, f23);
                        hp[0] = __floats2half2_rn(w01.x, w01.y);
                        hp[1] = __floats2half2_rn(w23.x, w23.y);
                        *(uint2*)(Mw + m * WORDN) = u;
                    }
                    *(float4*)&s_racc[e][half][lane * 4] = make_float4(r01.x, r01.y, r23.x, r23.y);
                }
                BARN(1 + e, 64);
                // combine read halves -> s_read + s_inh rows 64..
                {
                    int w = half * 32 + lane;
                    float s1 = s_racc[e][0][w] + s_racc[e][1][w];
                    s_read[e][w] = s1;
                    s_inh[e * STRX + 64 + w] = __float2half(s1);
                    int w2 = w + 64;
                    float s2 = s_racc[e][0][w2] + s_racc[e][1][w2];
                    s_read[e][w2] = s2;
                    s_inh[e * STRX + 64 + w2] = __float2half(s2);
                }
            }
        }
        __syncthreads();   // B4
    }

    // ---- epilogue ----
    for (int q = tid; q < BN; q += 512) {
        int u = unsort_idxs[q];
        if (u >= b0blk && u < b0blk + 4) s_dst[u - b0blk] = q;
    }
    __syncthreads();
    if (tig < 2) {
        #pragma unroll
        for (int c = 0; c < 4; ++c) {
            int jj = (c & 2) ? j1 : j0;
            int ee = (c & 1) ? e1 : e0;
            out[(size_t)s_dst[ee] * CTRLN + jj] = hreg[c];
        }
    }
    {
        int e = tid >> 7, w = tid & 127;
        if (tid < 512)
            out[(size_t)BN * CTRLN + (size_t)s_dst[e] * WORDN + w] = s_read[e][w];
    }
}

// ---------------- launch ----------------
extern "C" void kernel_launch(void* const* d_in, const int* in_sizes, int n_in,
                              void* d_out, int out_size) {
    const float* data        = (const float*)d_in[0];
    const int*   batch_sizes = (const int*)d_in[1];
    const int*   unsort      = (const int*)d_in[2];
    const float* W_ih        = (const float*)d_in[3];
    const float* b_ih        = (const float*)d_in[4];
    const float* W_hh        = (const float*)d_in[5];
    const float* b_hh        = (const float*)d_in[6];
    const float* W_key       = (const float*)d_in[7];
    const float* b_key       = (const float*)d_in[8];
    const float* W_beta      = (const float*)d_in[9];
    const float* b_beta      = (const float*)d_in[10];
    const float* W_erase     = (const float*)d_in[11];
    const float* b_erase     = (const float*)d_in[12];
    const float* W_add       = (const float*)d_in[13];
    const float* b_add       = (const float*)d_in[14];
    const float* M0          = (const float*)d_in[15];

    cudaFuncSetAttribute(ntm_main, cudaFuncAttributeMaxDynamicSharedMemorySize, SMEM_TOTAL);
    ntm_prep<<<256, 256>>>(W_ih, W_hh, W_key, W_beta, W_erase, W_add);
    ntm_main<<<128, 512, SMEM_TOTAL>>>(data, batch_sizes, unsort,
                                       b_ih, b_hh, b_key, b_beta, b_erase, b_add,
                                       M0, (float*)d_out);
}